// round 1
// baseline (speedup 1.0000x reference)
#include <cuda_runtime.h>
#include <cuda_bf16.h>
#include <math.h>

// ---------------- problem constants ----------------
constexpr int Bsz  = 2;
constexpr int Nq   = 2048;
constexpr int My   = 512;
constexpr int Cdim = 1536;
constexpr int Hn   = 12;
constexpr int HDim = 128;          // Cdim / Hn
constexpr int RD   = 64;
constexpr int Sk   = Nq + My;      // 2560
constexpr float EPSV  = 1e-6f;
constexpr float SCALE = 0.08838834764831845f;   // 1/sqrt(128)

// ---------------- scratch (static device arrays; no allocs allowed) ----------------
__device__ float g_qkv [(long long)Bsz * Nq * 3 * Cdim];        // 18.9M
__device__ float g_kvr [(long long)Bsz * My * 2 * Cdim];        // 3.1M
__device__ float g_Qb  [(long long)Bsz * Hn * Nq * HDim];       // 6.3M
__device__ float g_Kb  [(long long)Bsz * Hn * Sk * HDim];       // 7.9M
__device__ float g_Vb  [(long long)Bsz * Hn * Sk * HDim];       // 7.9M
__device__ float g_Sc  [(long long)Bsz * Hn * Nq * Sk];         // 125.8M (503MB)
__device__ float g_Ob  [(long long)Bsz * Nq * Cdim];            // 6.3M
__device__ float g_yb  [Bsz * My];

// ---------------- warp reduction helpers ----------------
__device__ __forceinline__ float warpSum(float v) {
    #pragma unroll
    for (int o = 16; o > 0; o >>= 1) v += __shfl_xor_sync(0xffffffffu, v, o);
    return v;
}
__device__ __forceinline__ float warpMax(float v) {
    #pragma unroll
    for (int o = 16; o > 0; o >>= 1) v = fmaxf(v, __shfl_xor_sync(0xffffffffu, v, o));
    return v;
}

// ---------------- generic batched 128x128x8 fp32 GEMM ----------------
// C[z] = A[z] @ B[z] (or A @ B^T if TRANS_B). All dims assumed multiples of tile sizes.
constexpr int GT = 128;   // tile
constexpr int GK = 8;     // k-step
constexpr int GP = 132;   // smem pad

template<bool TRANS_B, bool ADD_BIAS>
__global__ __launch_bounds__(256)
void sgemm(const float* __restrict__ A, const float* __restrict__ Bm,
           float* __restrict__ Cm, const float* __restrict__ bias,
           int Mr, int Nc, int Kd, int lda, int ldb, int ldc,
           long long sA, long long sB, long long sCout, long long sCin, int cPeriod)
{
    const int z = blockIdx.z;
    A  += (long long)z * sA;
    Bm += (long long)z * sB;
    Cm += (long long)(z / cPeriod) * sCout + (long long)(z % cPeriod) * sCin;

    __shared__ __align__(16) float As[GK][GP];
    __shared__ __align__(16) float Bs[GK][GP];

    const int tid  = threadIdx.x;
    const int row0 = blockIdx.y * GT;
    const int col0 = blockIdx.x * GT;

    // loader indices
    const int arow = tid >> 1;             // 0..127
    const int acol = (tid & 1) * 4;        // 0 or 4
    const int brow = tid >> 5;             // 0..7   (NN B load)
    const int bcol = (tid & 31) * 4;       // 0..124

    const int ty = tid >> 4;               // 0..15
    const int tx = tid & 15;               // 0..15

    float acc[8][8];
    #pragma unroll
    for (int i = 0; i < 8; i++)
        #pragma unroll
        for (int j = 0; j < 8; j++) acc[i][j] = 0.f;

    for (int k0 = 0; k0 < Kd; k0 += GK) {
        // A tile: 128 rows x 8 k, stored transposed As[k][m]
        {
            const float4 av = *(const float4*)(A + (long long)(row0 + arow) * lda + k0 + acol);
            As[acol + 0][arow] = av.x;
            As[acol + 1][arow] = av.y;
            As[acol + 2][arow] = av.z;
            As[acol + 3][arow] = av.w;
        }
        if (TRANS_B) {
            // B is [Nc, Kd] row-major: Bs[k][n] = B[n][k]
            const float4 bv = *(const float4*)(Bm + (long long)(col0 + arow) * ldb + k0 + acol);
            Bs[acol + 0][arow] = bv.x;
            Bs[acol + 1][arow] = bv.y;
            Bs[acol + 2][arow] = bv.z;
            Bs[acol + 3][arow] = bv.w;
        } else {
            // B is [Kd, Nc] row-major: Bs[k][n] = B[k][n]
            const float4 bv = *(const float4*)(Bm + (long long)(k0 + brow) * ldb + col0 + bcol);
            *(float4*)&Bs[brow][bcol] = bv;
        }
        __syncthreads();

        #pragma unroll
        for (int kk = 0; kk < GK; kk++) {
            float a[8], b[8];
            *(float4*)(a)     = *(const float4*)&As[kk][ty * 8];
            *(float4*)(a + 4) = *(const float4*)&As[kk][ty * 8 + 4];
            *(float4*)(b)     = *(const float4*)&Bs[kk][tx * 8];
            *(float4*)(b + 4) = *(const float4*)&Bs[kk][tx * 8 + 4];
            #pragma unroll
            for (int i = 0; i < 8; i++)
                #pragma unroll
                for (int j = 0; j < 8; j++)
                    acc[i][j] = fmaf(a[i], b[j], acc[i][j]);
        }
        __syncthreads();
    }

    float bv[8];
    if (ADD_BIAS) {
        #pragma unroll
        for (int j = 0; j < 8; j++) bv[j] = bias[col0 + tx * 8 + j];
    }

    #pragma unroll
    for (int i = 0; i < 8; i++) {
        const long long r = row0 + ty * 8 + i;
        float* cp = Cm + r * (long long)ldc + col0 + tx * 8;
        float4 o0, o1;
        o0.x = acc[i][0]; o0.y = acc[i][1]; o0.z = acc[i][2]; o0.w = acc[i][3];
        o1.x = acc[i][4]; o1.y = acc[i][5]; o1.z = acc[i][6]; o1.w = acc[i][7];
        if (ADD_BIAS) {
            o0.x += bv[0]; o0.y += bv[1]; o0.z += bv[2]; o0.w += bv[3];
            o1.x += bv[4]; o1.y += bv[5]; o1.z += bv[6]; o1.w += bv[7];
        }
        *(float4*)(cp)     = o0;
        *(float4*)(cp + 4) = o1;
    }
}

// ---------------- QKV postprocess: RMSNorm(q,k) + RoPE, scatter to head layout --------
__global__ void qkv_post(const float* __restrict__ qkv, const float* __restrict__ pos,
                         const float* __restrict__ qw, const float* __restrict__ kw,
                         float* __restrict__ Qb, float* __restrict__ Kb, float* __restrict__ Vb)
{
    const int idx = blockIdx.x;           // ((b*Nq + n)*Hn + h)
    const int h  = idx % Hn;
    const int bn = idx / Hn;
    const int n  = bn % Nq;
    const int b  = bn / Nq;
    const int d  = threadIdx.x;           // 0..127

    const float* row = qkv + (long long)bn * (3 * Cdim);
    const float qv = row[h * HDim + d];
    const float kv = row[Cdim + h * HDim + d];
    const float vv = row[2 * Cdim + h * HDim + d];

    __shared__ float sred[8];
    __shared__ float qs[HDim], ks[HDim];

    const float sq = warpSum(qv * qv);
    const float sk = warpSum(kv * kv);
    const int lane = d & 31, w = d >> 5;
    if (lane == 0) { sred[w] = sq; sred[4 + w] = sk; }
    __syncthreads();
    const float sumq = sred[0] + sred[1] + sred[2] + sred[3];
    const float sumk = sred[4] + sred[5] + sred[6] + sred[7];
    const float rq = rsqrtf(sumq * (1.0f / HDim) + EPSV);
    const float rk = rsqrtf(sumk * (1.0f / HDim) + EPSV);
    const float qn = qw[d] * qv * rq;
    const float kn = kw[d] * kv * rk;
    qs[d] = qn; ks[d] = kn;
    __syncthreads();

    float qo = qn, ko = kn;
    if (d < RD) {
        const int j = d & 31;
        const float c = pos[(n * 32 + j) * 2 + 0];
        const float s = pos[(n * 32 + j) * 2 + 1];
        if (d < RD / 2) { qo = qs[d] * c - qs[d + 32] * s;  ko = ks[d] * c - ks[d + 32] * s; }
        else            { qo = qs[d - 32] * s + qs[d] * c;  ko = ks[d - 32] * s + ks[d] * c; }
    }
    const long long qi = (((long long)(b * Hn + h)) * Nq + n) * HDim + d;
    const long long ki = (((long long)(b * Hn + h)) * Sk + n) * HDim + d;
    Qb[qi] = qo; Kb[ki] = ko; Vb[ki] = vv;
}

// ---------------- KV(y) postprocess: RMSNorm(k), scatter at s = Nq + m --------
__global__ void kv_post(const float* __restrict__ kvr, const float* __restrict__ kw,
                        float* __restrict__ Kb, float* __restrict__ Vb)
{
    const int idx = blockIdx.x;           // ((b*My + m)*Hn + h)
    const int h  = idx % Hn;
    const int bm = idx / Hn;
    const int m  = bm % My;
    const int b  = bm / My;
    const int d  = threadIdx.x;

    const float* row = kvr + (long long)bm * (2 * Cdim);
    const float kv = row[h * HDim + d];
    const float vv = row[Cdim + h * HDim + d];

    __shared__ float sred[4];
    const float sk = warpSum(kv * kv);
    if ((d & 31) == 0) sred[d >> 5] = sk;
    __syncthreads();
    const float sumk = sred[0] + sred[1] + sred[2] + sred[3];
    const float rk = rsqrtf(sumk * (1.0f / HDim) + EPSV);
    const float kn = kw[d] * kv * rk;

    const long long ki = (((long long)(b * Hn + h)) * Sk + (Nq + m)) * HDim + d;
    Kb[ki] = kn; Vb[ki] = vv;
}

// ---------------- y bias precompute ----------------
__global__ void ybias_kernel(const float* __restrict__ ytw, float* __restrict__ yb)
{
    const int i = blockIdx.x * blockDim.x + threadIdx.x;
    if (i < Bsz * My) yb[i] = logf(fmaxf(ytw[i], 1e-4f));
}

// ---------------- softmax over S (scale + bias fused) ----------------
__global__ __launch_bounds__(256)
void softmax_kernel(float* __restrict__ Sc, const float* __restrict__ yb)
{
    const long long row = blockIdx.x;                 // ((b*Hn+h)*Nq + n)
    const int b = (int)(row / ((long long)Hn * Nq));
    float* p = Sc + row * Sk;
    const int tid = threadIdx.x;

    float v[Sk / 256];                                // 10
    float mx = -1e30f;
    #pragma unroll
    for (int i = 0; i < Sk / 256; i++) {
        const int col = tid + i * 256;
        float t = p[col] * SCALE;
        if (col >= Nq) t += yb[b * My + col - Nq];
        v[i] = t; mx = fmaxf(mx, t);
    }

    __shared__ float s[8];
    mx = warpMax(mx);
    if ((tid & 31) == 0) s[tid >> 5] = mx;
    __syncthreads();
    float mfull = s[0];
    #pragma unroll
    for (int w = 1; w < 8; w++) mfull = fmaxf(mfull, s[w]);
    __syncthreads();

    float sum = 0.f;
    #pragma unroll
    for (int i = 0; i < Sk / 256; i++) { v[i] = __expf(v[i] - mfull); sum += v[i]; }
    sum = warpSum(sum);
    if ((tid & 31) == 0) s[tid >> 5] = sum;
    __syncthreads();
    float tot = s[0];
    #pragma unroll
    for (int w = 1; w < 8; w++) tot += s[w];
    const float inv = 1.0f / tot;

    #pragma unroll
    for (int i = 0; i < Sk / 256; i++) p[tid + i * 256] = v[i] * inv;
}

// ---------------- launch ----------------
extern "C" void kernel_launch(void* const* d_in, const int* in_sizes, int n_in,
                              void* d_out, int out_size)
{
    const float* x    = (const float*)d_in[0];
    const float* y    = (const float*)d_in[1];
    const float* pos  = (const float*)d_in[2];
    const float* ytw  = (const float*)d_in[3];
    const float* Wqkv = (const float*)d_in[4];
    const float* Wkv  = (const float*)d_in[5];
    const float* qw   = (const float*)d_in[6];
    const float* kw   = (const float*)d_in[7];
    const float* Wproj= (const float*)d_in[8];
    const float* bproj= (const float*)d_in[9];
    float* out = (float*)d_out;

    float *qkv, *kvr, *Qb, *Kb, *Vb, *Sc, *Ob, *yb;
    cudaGetSymbolAddress((void**)&qkv, g_qkv);
    cudaGetSymbolAddress((void**)&kvr, g_kvr);
    cudaGetSymbolAddress((void**)&Qb,  g_Qb);
    cudaGetSymbolAddress((void**)&Kb,  g_Kb);
    cudaGetSymbolAddress((void**)&Vb,  g_Vb);
    cudaGetSymbolAddress((void**)&Sc,  g_Sc);
    cudaGetSymbolAddress((void**)&Ob,  g_Ob);
    cudaGetSymbolAddress((void**)&yb,  g_yb);

    const long long sQ  = (long long)Nq * HDim;       // Qb batch stride
    const long long sKV = (long long)Sk * HDim;       // Kb/Vb batch stride
    const long long sSc = (long long)Nq * Sk;         // scores batch stride

    // 1) QKV = x @ Wqkv   [4096 x 4608, K=1536]
    sgemm<false, false><<<dim3(3 * Cdim / GT, Bsz * Nq / GT, 1), 256>>>(
        x, Wqkv, qkv, nullptr, Bsz * Nq, 3 * Cdim, Cdim,
        Cdim, 3 * Cdim, 3 * Cdim, 0, 0, 0, 0, 1);

    // 2) KV = y @ Wkv     [1024 x 3072, K=1536]
    sgemm<false, false><<<dim3(2 * Cdim / GT, Bsz * My / GT, 1), 256>>>(
        y, Wkv, kvr, nullptr, Bsz * My, 2 * Cdim, Cdim,
        Cdim, 2 * Cdim, 2 * Cdim, 0, 0, 0, 0, 1);

    // 3) postprocess
    qkv_post<<<Bsz * Nq * Hn, HDim>>>(qkv, pos, qw, kw, Qb, Kb, Vb);
    kv_post<<<Bsz * My * Hn, HDim>>>(kvr, kw, Kb, Vb);
    ybias_kernel<<<(Bsz * My + 255) / 256, 256>>>(ytw, yb);

    // 4) scores = Q @ K^T   batched over 24 (b,h): [2048 x 2560, K=128]
    sgemm<true, false><<<dim3(Sk / GT, Nq / GT, Bsz * Hn), 256>>>(
        Qb, Kb, Sc, nullptr, Nq, Sk, HDim,
        HDim, HDim, Sk, sQ, sKV, sSc, 0, 1);

    // 5) softmax (scale + bias fused)
    softmax_kernel<<<Bsz * Hn * Nq, 256>>>(Sc, yb);

    // 6) O = P @ V   batched: [2048 x 128, K=2560] -> scatter into [b][n][h*HD]
    sgemm<false, false><<<dim3(HDim / GT, Nq / GT, Bsz * Hn), 256>>>(
        Sc, Vb, Ob, nullptr, Nq, HDim, Sk,
        Sk, HDim, Cdim, sSc, sKV, (long long)Nq * Cdim, (long long)HDim, Hn);

    // 7) out = O @ Wproj + bproj   [4096 x 1536, K=1536]
    sgemm<false, true><<<dim3(Cdim / GT, Bsz * Nq / GT, 1), 256>>>(
        Ob, Wproj, out, bproj, Bsz * Nq, Cdim, Cdim,
        Cdim, Cdim, Cdim, 0, 0, 0, 0, 1);
}

// round 3
// speedup vs baseline: 1.4149x; 1.4149x over previous
#include <cuda_runtime.h>
#include <cuda_bf16.h>
#include <math.h>
#include <cstdint>

// ---------------- problem constants ----------------
constexpr int Bsz  = 2;
constexpr int Nq   = 2048;
constexpr int My   = 512;
constexpr int Cdim = 1536;
constexpr int Hn   = 12;
constexpr int HDim = 128;          // Cdim / Hn
constexpr int RD   = 64;
constexpr int Sk   = Nq + My;      // 2560
constexpr float EPSV  = 1e-6f;
constexpr float SCALE = 0.08838834764831845f;   // 1/sqrt(128)

// ---------------- scratch (static device arrays; no allocs allowed) ----------------
__device__ float g_qkv [(long long)Bsz * Nq * 3 * Cdim];
__device__ float g_kvr [(long long)Bsz * My * 2 * Cdim];
__device__ float g_Qb  [(long long)Bsz * Hn * Nq * HDim];
__device__ float g_Kb  [(long long)Bsz * Hn * Sk * HDim];
__device__ float g_Vb  [(long long)Bsz * Hn * Sk * HDim];
__device__ float g_Sc  [(long long)Bsz * Hn * Nq * Sk];
__device__ float g_Ob  [(long long)Bsz * Nq * Cdim];
__device__ float g_yb  [Bsz * My];

// split-bf16 operand buffers (weights stored TRANSPOSED: [N][K])
__device__ __nv_bfloat16 g_xh [(long long)Bsz * Nq * Cdim];
__device__ __nv_bfloat16 g_xl [(long long)Bsz * Nq * Cdim];
__device__ __nv_bfloat16 g_yh [(long long)Bsz * My * Cdim];
__device__ __nv_bfloat16 g_yl [(long long)Bsz * My * Cdim];
__device__ __nv_bfloat16 g_Wqkvh[(long long)3 * Cdim * Cdim];
__device__ __nv_bfloat16 g_Wqkvl[(long long)3 * Cdim * Cdim];
__device__ __nv_bfloat16 g_Wkvh [(long long)2 * Cdim * Cdim];
__device__ __nv_bfloat16 g_Wkvl [(long long)2 * Cdim * Cdim];
__device__ __nv_bfloat16 g_Wph  [(long long)Cdim * Cdim];
__device__ __nv_bfloat16 g_Wpl  [(long long)Cdim * Cdim];
__device__ __nv_bfloat16 g_Obh  [(long long)Bsz * Nq * Cdim];
__device__ __nv_bfloat16 g_Obl  [(long long)Bsz * Nq * Cdim];

// ---------------- small PTX helpers (baseline PTX only; no tcgen05) ----------------
__device__ __forceinline__ uint32_t smem_u32(const void* p) {
    uint32_t a;
    asm("{ .reg .u64 t; cvta.to.shared.u64 t, %1; cvt.u32.u64 %0, t; }" : "=r"(a) : "l"(p));
    return a;
}
__device__ __forceinline__ void cp16(uint32_t dst, const void* src) {
    asm volatile("cp.async.cg.shared.global [%0], [%1], 16;" :: "r"(dst), "l"(src));
}
#define CP_COMMIT()  asm volatile("cp.async.commit_group;" ::: "memory")
#define CP_WAIT(n)   asm volatile("cp.async.wait_group %0;" :: "n"(n) : "memory")

__device__ __forceinline__ void mma_bf16(float d[4], const uint32_t a[4], const uint32_t b[2]) {
    asm volatile(
        "mma.sync.aligned.m16n8k16.row.col.f32.bf16.bf16.f32 "
        "{%0,%1,%2,%3}, {%4,%5,%6,%7}, {%8,%9}, {%0,%1,%2,%3};"
        : "+f"(d[0]), "+f"(d[1]), "+f"(d[2]), "+f"(d[3])
        : "r"(a[0]), "r"(a[1]), "r"(a[2]), "r"(a[3]), "r"(b[0]), "r"(b[1]));
}

// ---------------- split-bf16 HMMA GEMM ----------------
// C[M,N] = A[M,K] @ W[K,N], where A given as (Ah,Al) row-major [M,K] and
// W given as (Bh,Bl) TRANSPOSED row-major [N,K]. fp32 accumulate, 3-product split.
// CTA tile 128x128, 8 warps (warp tile 64x32), K-chunk 32, double-buffered cp.async.
constexpr int MM_STRIDE_B = 80;                         // 40 bf16 per smem row
constexpr int MM_ARR_B    = 128 * MM_STRIDE_B;          // 10240 per operand array
constexpr int MM_BUF_B    = 4 * MM_ARR_B;               // Ah,Al,Bh,Bl
constexpr int MM_SMEM_B   = 2 * MM_BUF_B;               // 81920

template<bool ADD_BIAS>
__global__ __launch_bounds__(256)
void mma_gemm(const __nv_bfloat16* __restrict__ Ah, const __nv_bfloat16* __restrict__ Al,
              const __nv_bfloat16* __restrict__ Bh, const __nv_bfloat16* __restrict__ Bl,
              float* __restrict__ C, const float* __restrict__ bias,
              int Kd, int ldc)
{
    extern __shared__ char smem[];
    const uint32_t sbase = smem_u32(smem);

    const int tid  = threadIdx.x;
    const int lane = tid & 31;
    const int wid  = tid >> 5;
    const int row0 = blockIdx.y * 128;
    const int col0 = blockIdx.x * 128;
    const int wm   = (wid >> 2) * 64;     // 0 / 64
    const int wn   = (wid & 3) * 32;      // 0..96
    const int g    = lane >> 2;           // 0..7
    const int tg   = lane & 3;            // 0..3

    // staging map: each thread moves 2 16B segments per operand array per chunk
    const int s0   = tid * 2;
    const int row_s0 = s0 >> 2,  q_s0 = s0 & 3;
    const int row_s1 = (s0 + 1) >> 2, q_s1 = (s0 + 1) & 3;

    auto stage = [&](int c, int buf) {
        const long long k0 = (long long)c * 32;
        const uint32_t db = sbase + buf * MM_BUF_B;
        // seg 0
        {
            const long long ga = (long long)(row0 + row_s0) * Kd + k0 + q_s0 * 8;
            const long long gb = (long long)(col0 + row_s0) * Kd + k0 + q_s0 * 8;
            const uint32_t  so = row_s0 * MM_STRIDE_B + q_s0 * 16;
            cp16(db + 0 * MM_ARR_B + so, Ah + ga);
            cp16(db + 1 * MM_ARR_B + so, Al + ga);
            cp16(db + 2 * MM_ARR_B + so, Bh + gb);
            cp16(db + 3 * MM_ARR_B + so, Bl + gb);
        }
        // seg 1
        {
            const long long ga = (long long)(row0 + row_s1) * Kd + k0 + q_s1 * 8;
            const long long gb = (long long)(col0 + row_s1) * Kd + k0 + q_s1 * 8;
            const uint32_t  so = row_s1 * MM_STRIDE_B + q_s1 * 16;
            cp16(db + 0 * MM_ARR_B + so, Ah + ga);
            cp16(db + 1 * MM_ARR_B + so, Al + ga);
            cp16(db + 2 * MM_ARR_B + so, Bh + gb);
            cp16(db + 3 * MM_ARR_B + so, Bl + gb);
        }
    };

    float acc[4][4][4];
    #pragma unroll
    for (int i = 0; i < 4; i++)
        #pragma unroll
        for (int j = 0; j < 4; j++)
            #pragma unroll
            for (int r = 0; r < 4; r++) acc[i][j][r] = 0.f;

    const int nch = Kd / 32;
    stage(0, 0);
    CP_COMMIT();

    for (int c = 0; c < nch; c++) {
        if (c + 1 < nch) { stage(c + 1, (c + 1) & 1); CP_COMMIT(); CP_WAIT(1); }
        else             { CP_WAIT(0); }
        __syncthreads();

        const char* bp = smem + (c & 1) * MM_BUF_B;
        const char* pAh = bp;
        const char* pAl = bp + MM_ARR_B;
        const char* pBh = bp + 2 * MM_ARR_B;
        const char* pBl = bp + 3 * MM_ARR_B;

        #pragma unroll
        for (int kk = 0; kk < 2; kk++) {
            const int cbyte = (kk * 16 + 2 * tg) * 2;
            uint32_t ah[4][4], al[4][4], bh[4][2], bl[4][2];
            #pragma unroll
            for (int mt = 0; mt < 4; mt++) {
                const int r = wm + mt * 16 + g;
                ah[mt][0] = *(const uint32_t*)(pAh + r * MM_STRIDE_B + cbyte);
                ah[mt][1] = *(const uint32_t*)(pAh + (r + 8) * MM_STRIDE_B + cbyte);
                ah[mt][2] = *(const uint32_t*)(pAh + r * MM_STRIDE_B + cbyte + 16);
                ah[mt][3] = *(const uint32_t*)(pAh + (r + 8) * MM_STRIDE_B + cbyte + 16);
                al[mt][0] = *(const uint32_t*)(pAl + r * MM_STRIDE_B + cbyte);
                al[mt][1] = *(const uint32_t*)(pAl + (r + 8) * MM_STRIDE_B + cbyte);
                al[mt][2] = *(const uint32_t*)(pAl + r * MM_STRIDE_B + cbyte + 16);
                al[mt][3] = *(const uint32_t*)(pAl + (r + 8) * MM_STRIDE_B + cbyte + 16);
            }
            #pragma unroll
            for (int nt = 0; nt < 4; nt++) {
                const int n = wn + nt * 8 + g;
                bh[nt][0] = *(const uint32_t*)(pBh + n * MM_STRIDE_B + cbyte);
                bh[nt][1] = *(const uint32_t*)(pBh + n * MM_STRIDE_B + cbyte + 16);
                bl[nt][0] = *(const uint32_t*)(pBl + n * MM_STRIDE_B + cbyte);
                bl[nt][1] = *(const uint32_t*)(pBl + n * MM_STRIDE_B + cbyte + 16);
            }
            #pragma unroll
            for (int mt = 0; mt < 4; mt++)
                #pragma unroll
                for (int nt = 0; nt < 4; nt++) {
                    mma_bf16(acc[mt][nt], ah[mt], bh[nt]);
                    mma_bf16(acc[mt][nt], ah[mt], bl[nt]);
                    mma_bf16(acc[mt][nt], al[mt], bh[nt]);
                }
        }
        __syncthreads();
    }

    // ---- epilogue ----
    #pragma unroll
    for (int nt = 0; nt < 4; nt++) {
        const int col = col0 + wn + nt * 8 + 2 * tg;
        float b0 = 0.f, b1 = 0.f;
        if (ADD_BIAS) { b0 = bias[col]; b1 = bias[col + 1]; }
        #pragma unroll
        for (int mt = 0; mt < 4; mt++) {
            const int r = row0 + wm + mt * 16 + g;
            float2 v0, v1;
            v0.x = acc[mt][nt][0] + b0; v0.y = acc[mt][nt][1] + b1;
            v1.x = acc[mt][nt][2] + b0; v1.y = acc[mt][nt][3] + b1;
            *(float2*)(C + (long long)r * ldc + col)       = v0;
            *(float2*)(C + (long long)(r + 8) * ldc + col) = v1;
        }
    }
}

// ---------------- fp32 -> split bf16 (row-major keep) ----------------
__global__ void cvt_split(const float* __restrict__ src, __nv_bfloat16* __restrict__ h,
                          __nv_bfloat16* __restrict__ l, long long n)
{
    const long long i = ((long long)blockIdx.x * blockDim.x + threadIdx.x) * 4;
    if (i >= n) return;
    const float4 v = *(const float4*)(src + i);
    __nv_bfloat16 hb[4], lb[4];
    const float f[4] = {v.x, v.y, v.z, v.w};
    #pragma unroll
    for (int j = 0; j < 4; j++) {
        hb[j] = __float2bfloat16(f[j]);
        lb[j] = __float2bfloat16(f[j] - __bfloat162float(hb[j]));
    }
    *(uint2*)(h + i) = *(uint2*)hb;
    *(uint2*)(l + i) = *(uint2*)lb;
}

// ---------------- fp32 [K][N] -> split bf16 transposed [N][K] ----------------
__global__ void cvt_split_T(const float* __restrict__ W, __nv_bfloat16* __restrict__ h,
                            __nv_bfloat16* __restrict__ l, int K, int N)
{
    __shared__ float tile[32][33];
    const int k0 = blockIdx.y * 32;
    const int n0 = blockIdx.x * 32;
    const int tx = threadIdx.x;       // 32
    const int ty = threadIdx.y;       // 8
    #pragma unroll
    for (int i = ty; i < 32; i += 8)
        tile[i][tx] = W[(long long)(k0 + i) * N + n0 + tx];
    __syncthreads();
    #pragma unroll
    for (int i = ty; i < 32; i += 8) {
        const float v = tile[tx][i];              // W[k0+tx][n0+i]
        const __nv_bfloat16 hb = __float2bfloat16(v);
        const __nv_bfloat16 lb = __float2bfloat16(v - __bfloat162float(hb));
        const long long o = (long long)(n0 + i) * K + k0 + tx;
        h[o] = hb; l[o] = lb;
    }
}

// ---------------- warp reduction helpers ----------------
__device__ __forceinline__ float warpSum(float v) {
    #pragma unroll
    for (int o = 16; o > 0; o >>= 1) v += __shfl_xor_sync(0xffffffffu, v, o);
    return v;
}
__device__ __forceinline__ float warpMax(float v) {
    #pragma unroll
    for (int o = 16; o > 0; o >>= 1) v = fmaxf(v, __shfl_xor_sync(0xffffffffu, v, o));
    return v;
}

// ---------------- generic batched 128x128x8 fp32 GEMM (attention) ----------------
constexpr int GT = 128;
constexpr int GK = 8;
constexpr int GP = 132;

template<bool TRANS_B>
__global__ __launch_bounds__(256)
void sgemm(const float* __restrict__ A, const float* __restrict__ Bm,
           float* __restrict__ Cm,
           int Kd, int lda, int ldb, int ldc,
           long long sA, long long sB, long long sCout, long long sCin, int cPeriod)
{
    const int z = blockIdx.z;
    A  += (long long)z * sA;
    Bm += (long long)z * sB;
    Cm += (long long)(z / cPeriod) * sCout + (long long)(z % cPeriod) * sCin;

    __shared__ __align__(16) float As[GK][GP];
    __shared__ __align__(16) float Bs[GK][GP];

    const int tid  = threadIdx.x;
    const int row0 = blockIdx.y * GT;
    const int col0 = blockIdx.x * GT;

    const int arow = tid >> 1;
    const int acol = (tid & 1) * 4;
    const int brow = tid >> 5;
    const int bcol = (tid & 31) * 4;
    const int ty = tid >> 4;
    const int tx = tid & 15;

    float acc[8][8];
    #pragma unroll
    for (int i = 0; i < 8; i++)
        #pragma unroll
        for (int j = 0; j < 8; j++) acc[i][j] = 0.f;

    for (int k0 = 0; k0 < Kd; k0 += GK) {
        {
            const float4 av = *(const float4*)(A + (long long)(row0 + arow) * lda + k0 + acol);
            As[acol + 0][arow] = av.x; As[acol + 1][arow] = av.y;
            As[acol + 2][arow] = av.z; As[acol + 3][arow] = av.w;
        }
        if (TRANS_B) {
            const float4 bv = *(const float4*)(Bm + (long long)(col0 + arow) * ldb + k0 + acol);
            Bs[acol + 0][arow] = bv.x; Bs[acol + 1][arow] = bv.y;
            Bs[acol + 2][arow] = bv.z; Bs[acol + 3][arow] = bv.w;
        } else {
            const float4 bv = *(const float4*)(Bm + (long long)(k0 + brow) * ldb + col0 + bcol);
            *(float4*)&Bs[brow][bcol] = bv;
        }
        __syncthreads();

        #pragma unroll
        for (int kk = 0; kk < GK; kk++) {
            float a[8], b[8];
            *(float4*)(a)     = *(const float4*)&As[kk][ty * 8];
            *(float4*)(a + 4) = *(const float4*)&As[kk][ty * 8 + 4];
            *(float4*)(b)     = *(const float4*)&Bs[kk][tx * 8];
            *(float4*)(b + 4) = *(const float4*)&Bs[kk][tx * 8 + 4];
            #pragma unroll
            for (int i = 0; i < 8; i++)
                #pragma unroll
                for (int j = 0; j < 8; j++)
                    acc[i][j] = fmaf(a[i], b[j], acc[i][j]);
        }
        __syncthreads();
    }

    #pragma unroll
    for (int i = 0; i < 8; i++) {
        const long long r = row0 + ty * 8 + i;
        float* cp = Cm + r * (long long)ldc + col0 + tx * 8;
        float4 o0, o1;
        o0.x = acc[i][0]; o0.y = acc[i][1]; o0.z = acc[i][2]; o0.w = acc[i][3];
        o1.x = acc[i][4]; o1.y = acc[i][5]; o1.z = acc[i][6]; o1.w = acc[i][7];
        *(float4*)(cp)     = o0;
        *(float4*)(cp + 4) = o1;
    }
}

// ---------------- QKV postprocess ----------------
__global__ void qkv_post(const float* __restrict__ qkv, const float* __restrict__ pos,
                         const float* __restrict__ qw, const float* __restrict__ kw,
                         float* __restrict__ Qb, float* __restrict__ Kb, float* __restrict__ Vb)
{
    const int idx = blockIdx.x;
    const int h  = idx % Hn;
    const int bn = idx / Hn;
    const int n  = bn % Nq;
    const int b  = bn / Nq;
    const int d  = threadIdx.x;

    const float* row = qkv + (long long)bn * (3 * Cdim);
    const float qv = row[h * HDim + d];
    const float kv = row[Cdim + h * HDim + d];
    const float vv = row[2 * Cdim + h * HDim + d];

    __shared__ float sred[8];
    __shared__ float qs[HDim], ks[HDim];

    const float sq = warpSum(qv * qv);
    const float sk = warpSum(kv * kv);
    const int lane = d & 31, w = d >> 5;
    if (lane == 0) { sred[w] = sq; sred[4 + w] = sk; }
    __syncthreads();
    const float sumq = sred[0] + sred[1] + sred[2] + sred[3];
    const float sumk = sred[4] + sred[5] + sred[6] + sred[7];
    const float rq = rsqrtf(sumq * (1.0f / HDim) + EPSV);
    const float rk = rsqrtf(sumk * (1.0f / HDim) + EPSV);
    const float qn = qw[d] * qv * rq;
    const float kn = kw[d] * kv * rk;
    qs[d] = qn; ks[d] = kn;
    __syncthreads();

    float qo = qn, ko = kn;
    if (d < RD) {
        const int j = d & 31;
        const float c = pos[(n * 32 + j) * 2 + 0];
        const float s = pos[(n * 32 + j) * 2 + 1];
        if (d < RD / 2) { qo = qs[d] * c - qs[d + 32] * s;  ko = ks[d] * c - ks[d + 32] * s; }
        else            { qo = qs[d - 32] * s + qs[d] * c;  ko = ks[d - 32] * s + ks[d] * c; }
    }
    const long long qi = (((long long)(b * Hn + h)) * Nq + n) * HDim + d;
    const long long ki = (((long long)(b * Hn + h)) * Sk + n) * HDim + d;
    Qb[qi] = qo; Kb[ki] = ko; Vb[ki] = vv;
}

__global__ void kv_post(const float* __restrict__ kvr, const float* __restrict__ kw,
                        float* __restrict__ Kb, float* __restrict__ Vb)
{
    const int idx = blockIdx.x;
    const int h  = idx % Hn;
    const int bm = idx / Hn;
    const int m  = bm % My;
    const int b  = bm / My;
    const int d  = threadIdx.x;

    const float* row = kvr + (long long)bm * (2 * Cdim);
    const float kv = row[h * HDim + d];
    const float vv = row[Cdim + h * HDim + d];

    __shared__ float sred[4];
    const float sk = warpSum(kv * kv);
    if ((d & 31) == 0) sred[d >> 5] = sk;
    __syncthreads();
    const float sumk = sred[0] + sred[1] + sred[2] + sred[3];
    const float rk = rsqrtf(sumk * (1.0f / HDim) + EPSV);
    const float kn = kw[d] * kv * rk;

    const long long ki = (((long long)(b * Hn + h)) * Sk + (Nq + m)) * HDim + d;
    Kb[ki] = kn; Vb[ki] = vv;
}

__global__ void ybias_kernel(const float* __restrict__ ytw, float* __restrict__ yb)
{
    const int i = blockIdx.x * blockDim.x + threadIdx.x;
    if (i < Bsz * My) yb[i] = logf(fmaxf(ytw[i], 1e-4f));
}

// ---------------- softmax ----------------
__global__ __launch_bounds__(256)
void softmax_kernel(float* __restrict__ Sc, const float* __restrict__ yb)
{
    const long long row = blockIdx.x;
    const int b = (int)(row / ((long long)Hn * Nq));
    float* p = Sc + row * Sk;
    const int tid = threadIdx.x;

    float v[Sk / 256];
    float mx = -1e30f;
    #pragma unroll
    for (int i = 0; i < Sk / 256; i++) {
        const int col = tid + i * 256;
        float t = p[col] * SCALE;
        if (col >= Nq) t += yb[b * My + col - Nq];
        v[i] = t; mx = fmaxf(mx, t);
    }

    __shared__ float s[8];
    mx = warpMax(mx);
    if ((tid & 31) == 0) s[tid >> 5] = mx;
    __syncthreads();
    float mfull = s[0];
    #pragma unroll
    for (int w = 1; w < 8; w++) mfull = fmaxf(mfull, s[w]);
    __syncthreads();

    float sum = 0.f;
    #pragma unroll
    for (int i = 0; i < Sk / 256; i++) { v[i] = __expf(v[i] - mfull); sum += v[i]; }
    sum = warpSum(sum);
    if ((tid & 31) == 0) s[tid >> 5] = sum;
    __syncthreads();
    float tot = s[0];
    #pragma unroll
    for (int w = 1; w < 8; w++) tot += s[w];
    const float inv = 1.0f / tot;

    #pragma unroll
    for (int i = 0; i < Sk / 256; i++) p[tid + i * 256] = v[i] * inv;
}

// ---------------- launch ----------------
extern "C" void kernel_launch(void* const* d_in, const int* in_sizes, int n_in,
                              void* d_out, int out_size)
{
    const float* x    = (const float*)d_in[0];
    const float* y    = (const float*)d_in[1];
    const float* pos  = (const float*)d_in[2];
    const float* ytw  = (const float*)d_in[3];
    const float* Wqkv = (const float*)d_in[4];
    const float* Wkv  = (const float*)d_in[5];
    const float* qw   = (const float*)d_in[6];
    const float* kw   = (const float*)d_in[7];
    const float* Wproj= (const float*)d_in[8];
    const float* bproj= (const float*)d_in[9];
    float* out = (float*)d_out;

    float *qkv, *kvr, *Qb, *Kb, *Vb, *Sc, *Ob, *yb;
    cudaGetSymbolAddress((void**)&qkv, g_qkv);
    cudaGetSymbolAddress((void**)&kvr, g_kvr);
    cudaGetSymbolAddress((void**)&Qb,  g_Qb);
    cudaGetSymbolAddress((void**)&Kb,  g_Kb);
    cudaGetSymbolAddress((void**)&Vb,  g_Vb);
    cudaGetSymbolAddress((void**)&Sc,  g_Sc);
    cudaGetSymbolAddress((void**)&Ob,  g_Ob);
    cudaGetSymbolAddress((void**)&yb,  g_yb);

    __nv_bfloat16 *xh,*xl,*yh,*yl,*Wqh,*Wql,*Wkh,*Wkl,*Wph,*Wpl,*Obh,*Obl;
    cudaGetSymbolAddress((void**)&xh, g_xh);   cudaGetSymbolAddress((void**)&xl, g_xl);
    cudaGetSymbolAddress((void**)&yh, g_yh);   cudaGetSymbolAddress((void**)&yl, g_yl);
    cudaGetSymbolAddress((void**)&Wqh, g_Wqkvh); cudaGetSymbolAddress((void**)&Wql, g_Wqkvl);
    cudaGetSymbolAddress((void**)&Wkh, g_Wkvh);  cudaGetSymbolAddress((void**)&Wkl, g_Wkvl);
    cudaGetSymbolAddress((void**)&Wph, g_Wph);   cudaGetSymbolAddress((void**)&Wpl, g_Wpl);
    cudaGetSymbolAddress((void**)&Obh, g_Obh);   cudaGetSymbolAddress((void**)&Obl, g_Obl);

    cudaFuncSetAttribute(mma_gemm<false>, cudaFuncAttributeMaxDynamicSharedMemorySize, MM_SMEM_B);
    cudaFuncSetAttribute(mma_gemm<true>,  cudaFuncAttributeMaxDynamicSharedMemorySize, MM_SMEM_B);

    const long long sQ  = (long long)Nq * HDim;
    const long long sKV = (long long)Sk * HDim;
    const long long sSc = (long long)Nq * Sk;

    // 0) split conversions: activations row-major, weights transposed to [N][K]
    auto cvt = [&](const float* s, __nv_bfloat16* h, __nv_bfloat16* l, long long n) {
        cvt_split<<<(int)((n / 4 + 255) / 256), 256>>>(s, h, l, n);
    };
    cvt(x, xh, xl, (long long)Bsz * Nq * Cdim);
    cvt(y, yh, yl, (long long)Bsz * My * Cdim);
    cvt_split_T<<<dim3(3 * Cdim / 32, Cdim / 32), dim3(32, 8)>>>(Wqkv, Wqh, Wql, Cdim, 3 * Cdim);
    cvt_split_T<<<dim3(2 * Cdim / 32, Cdim / 32), dim3(32, 8)>>>(Wkv,  Wkh, Wkl, Cdim, 2 * Cdim);
    cvt_split_T<<<dim3(Cdim / 32,     Cdim / 32), dim3(32, 8)>>>(Wproj, Wph, Wpl, Cdim, Cdim);

    // 1) QKV = x @ Wqkv   [4096 x 4608, K=1536]  (HMMA split-bf16)
    mma_gemm<false><<<dim3(3 * Cdim / 128, Bsz * Nq / 128), 256, MM_SMEM_B>>>(
        xh, xl, Wqh, Wql, qkv, nullptr, Cdim, 3 * Cdim);

    // 2) KV = y @ Wkv     [1024 x 3072, K=1536]  (HMMA split-bf16)
    mma_gemm<false><<<dim3(2 * Cdim / 128, Bsz * My / 128), 256, MM_SMEM_B>>>(
        yh, yl, Wkh, Wkl, kvr, nullptr, Cdim, 2 * Cdim);

    // 3) postprocess
    qkv_post<<<Bsz * Nq * Hn, HDim>>>(qkv, pos, qw, kw, Qb, Kb, Vb);
    kv_post<<<Bsz * My * Hn, HDim>>>(kvr, kw, Kb, Vb);
    ybias_kernel<<<(Bsz * My + 255) / 256, 256>>>(ytw, yb);

    // 4) scores = Q @ K^T  batched over 24 (b,h)
    sgemm<true><<<dim3(Sk / GT, Nq / GT, Bsz * Hn), 256>>>(
        Qb, Kb, Sc, HDim, HDim, HDim, Sk, sQ, sKV, sSc, 0, 1);

    // 5) softmax
    softmax_kernel<<<Bsz * Hn * Nq, 256>>>(Sc, yb);

    // 6) O = P @ V  batched -> [b][n][h*HD]
    sgemm<false><<<dim3(HDim / GT, Nq / GT, Bsz * Hn), 256>>>(
        Sc, Vb, Ob, Sk, Sk, HDim, Cdim, sSc, sKV, (long long)Nq * Cdim, (long long)HDim, Hn);

    // 7) convert O, then out = O @ Wproj^T-layout + bproj (HMMA split-bf16)
    cvt(Ob, Obh, Obl, (long long)Bsz * Nq * Cdim);
    mma_gemm<true><<<dim3(Cdim / 128, Bsz * Nq / 128), 256, MM_SMEM_B>>>(
        Obh, Obl, Wph, Wpl, out, bproj, Cdim, Cdim);
}

// round 4
// speedup vs baseline: 2.2046x; 1.5582x over previous
#include <cuda_runtime.h>
#include <cuda_bf16.h>
#include <math.h>
#include <cstdint>

// ---------------- problem constants ----------------
constexpr int Bsz  = 2;
constexpr int Nq   = 2048;
constexpr int My   = 512;
constexpr int Cdim = 1536;
constexpr int Hn   = 12;
constexpr int HDim = 128;          // Cdim / Hn
constexpr int RD   = 64;
constexpr int Sk   = Nq + My;      // 2560
constexpr float EPSV  = 1e-6f;
constexpr float SCALE = 0.08838834764831845f;   // 1/sqrt(128)

// ---------------- scratch (static device arrays; no allocs allowed) ----------------
__device__ float g_qkv [(long long)Bsz * Nq * 3 * Cdim];
__device__ float g_kvr [(long long)Bsz * My * 2 * Cdim];
__device__ float g_Vb  [(long long)Bsz * Hn * Sk * HDim];   // V fp32 [bh][s][d]
__device__ float g_Sc  [(long long)Bsz * Hn * Nq * Sk];     // scores fp32
__device__ float g_Ob  [(long long)Bsz * Nq * Cdim];
__device__ float g_yb  [Bsz * My];

// split-bf16 operand buffers
__device__ __nv_bfloat16 g_xh [(long long)Bsz * Nq * Cdim];
__device__ __nv_bfloat16 g_xl [(long long)Bsz * Nq * Cdim];
__device__ __nv_bfloat16 g_yh [(long long)Bsz * My * Cdim];
__device__ __nv_bfloat16 g_yl [(long long)Bsz * My * Cdim];
__device__ __nv_bfloat16 g_Wqkvh[(long long)3 * Cdim * Cdim];
__device__ __nv_bfloat16 g_Wqkvl[(long long)3 * Cdim * Cdim];
__device__ __nv_bfloat16 g_Wkvh [(long long)2 * Cdim * Cdim];
__device__ __nv_bfloat16 g_Wkvl [(long long)2 * Cdim * Cdim];
__device__ __nv_bfloat16 g_Wph  [(long long)Cdim * Cdim];
__device__ __nv_bfloat16 g_Wpl  [(long long)Cdim * Cdim];
__device__ __nv_bfloat16 g_Obh  [(long long)Bsz * Nq * Cdim];
__device__ __nv_bfloat16 g_Obl  [(long long)Bsz * Nq * Cdim];
// attention split operands
__device__ __nv_bfloat16 g_Qh [(long long)Bsz * Hn * Nq * HDim];
__device__ __nv_bfloat16 g_Ql [(long long)Bsz * Hn * Nq * HDim];
__device__ __nv_bfloat16 g_Kh [(long long)Bsz * Hn * Sk * HDim];
__device__ __nv_bfloat16 g_Kl [(long long)Bsz * Hn * Sk * HDim];
__device__ __nv_bfloat16 g_Vth[(long long)Bsz * Hn * HDim * Sk];  // V^T [bh][d][s]
__device__ __nv_bfloat16 g_Vtl[(long long)Bsz * Hn * HDim * Sk];
__device__ __nv_bfloat16 g_Ph [(long long)Bsz * Hn * Nq * Sk];
__device__ __nv_bfloat16 g_Pl [(long long)Bsz * Hn * Nq * Sk];

// ---------------- small PTX helpers (baseline PTX only) ----------------
__device__ __forceinline__ uint32_t smem_u32(const void* p) {
    uint32_t a;
    asm("{ .reg .u64 t; cvta.to.shared.u64 t, %1; cvt.u32.u64 %0, t; }" : "=r"(a) : "l"(p));
    return a;
}
__device__ __forceinline__ void cp16(uint32_t dst, const void* src) {
    asm volatile("cp.async.cg.shared.global [%0], [%1], 16;" :: "r"(dst), "l"(src));
}
#define CP_COMMIT()  asm volatile("cp.async.commit_group;" ::: "memory")
#define CP_WAIT(n)   asm volatile("cp.async.wait_group %0;" :: "n"(n) : "memory")

__device__ __forceinline__ void mma_bf16(float d[4], const uint32_t a[4], const uint32_t b[2]) {
    asm volatile(
        "mma.sync.aligned.m16n8k16.row.col.f32.bf16.bf16.f32 "
        "{%0,%1,%2,%3}, {%4,%5,%6,%7}, {%8,%9}, {%0,%1,%2,%3};"
        : "+f"(d[0]), "+f"(d[1]), "+f"(d[2]), "+f"(d[3])
        : "r"(a[0]), "r"(a[1]), "r"(a[2]), "r"(a[3]), "r"(b[0]), "r"(b[1]));
}

// ---------------- split-bf16 HMMA GEMM (batched) ----------------
// C[M,N] = A[M,K] @ W[K,N]; A=(Ah,Al) row-major [M,K] (lda==Kd);
// W=(Bh,Bl) row-major TRANSPOSED [N,K] (ldb==Kd). fp32 accumulate, 3-product split.
// Batched over blockIdx.z with element strides sA (A), sB (B) and
// C += (z/cPeriod)*sCout + (z%cPeriod)*sCin.
constexpr int MM_STRIDE_B = 80;                         // 40 bf16 per smem row
constexpr int MM_ARR_B    = 128 * MM_STRIDE_B;          // 10240 per operand array
constexpr int MM_BUF_B    = 4 * MM_ARR_B;               // Ah,Al,Bh,Bl
constexpr int MM_SMEM_B   = 2 * MM_BUF_B;               // 81920

template<bool ADD_BIAS>
__global__ __launch_bounds__(256)
void mma_gemm(const __nv_bfloat16* __restrict__ Ah, const __nv_bfloat16* __restrict__ Al,
              const __nv_bfloat16* __restrict__ Bh, const __nv_bfloat16* __restrict__ Bl,
              float* __restrict__ C, const float* __restrict__ bias,
              int Kd, int ldc,
              long long sA, long long sB, long long sCout, long long sCin, int cPeriod)
{
    extern __shared__ char smem[];
    const uint32_t sbase = smem_u32(smem);

    const int z = blockIdx.z;
    Ah += (long long)z * sA;  Al += (long long)z * sA;
    Bh += (long long)z * sB;  Bl += (long long)z * sB;
    C  += (long long)(z / cPeriod) * sCout + (long long)(z % cPeriod) * sCin;

    const int tid  = threadIdx.x;
    const int lane = tid & 31;
    const int wid  = tid >> 5;
    const int row0 = blockIdx.y * 128;
    const int col0 = blockIdx.x * 128;
    const int wm   = (wid >> 2) * 64;     // 0 / 64
    const int wn   = (wid & 3) * 32;      // 0..96
    const int g    = lane >> 2;           // 0..7
    const int tg   = lane & 3;            // 0..3

    // staging map: each thread moves 2 16B segments per operand array per chunk
    const int s0   = tid * 2;
    const int row_s0 = s0 >> 2,  q_s0 = s0 & 3;
    const int row_s1 = (s0 + 1) >> 2, q_s1 = (s0 + 1) & 3;

    auto stage = [&](int c, int buf) {
        const long long k0 = (long long)c * 32;
        const uint32_t db = sbase + buf * MM_BUF_B;
        {
            const long long ga = (long long)(row0 + row_s0) * Kd + k0 + q_s0 * 8;
            const long long gb = (long long)(col0 + row_s0) * Kd + k0 + q_s0 * 8;
            const uint32_t  so = row_s0 * MM_STRIDE_B + q_s0 * 16;
            cp16(db + 0 * MM_ARR_B + so, Ah + ga);
            cp16(db + 1 * MM_ARR_B + so, Al + ga);
            cp16(db + 2 * MM_ARR_B + so, Bh + gb);
            cp16(db + 3 * MM_ARR_B + so, Bl + gb);
        }
        {
            const long long ga = (long long)(row0 + row_s1) * Kd + k0 + q_s1 * 8;
            const long long gb = (long long)(col0 + row_s1) * Kd + k0 + q_s1 * 8;
            const uint32_t  so = row_s1 * MM_STRIDE_B + q_s1 * 16;
            cp16(db + 0 * MM_ARR_B + so, Ah + ga);
            cp16(db + 1 * MM_ARR_B + so, Al + ga);
            cp16(db + 2 * MM_ARR_B + so, Bh + gb);
            cp16(db + 3 * MM_ARR_B + so, Bl + gb);
        }
    };

    float acc[4][4][4];
    #pragma unroll
    for (int i = 0; i < 4; i++)
        #pragma unroll
        for (int j = 0; j < 4; j++)
            #pragma unroll
            for (int r = 0; r < 4; r++) acc[i][j][r] = 0.f;

    const int nch = Kd / 32;
    stage(0, 0);
    CP_COMMIT();

    for (int c = 0; c < nch; c++) {
        if (c + 1 < nch) { stage(c + 1, (c + 1) & 1); CP_COMMIT(); CP_WAIT(1); }
        else             { CP_WAIT(0); }
        __syncthreads();

        const char* bp = smem + (c & 1) * MM_BUF_B;
        const char* pAh = bp;
        const char* pAl = bp + MM_ARR_B;
        const char* pBh = bp + 2 * MM_ARR_B;
        const char* pBl = bp + 3 * MM_ARR_B;

        #pragma unroll
        for (int kk = 0; kk < 2; kk++) {
            const int cbyte = (kk * 16 + 2 * tg) * 2;
            uint32_t ah[4][4], al[4][4], bh[4][2], bl[4][2];
            #pragma unroll
            for (int mt = 0; mt < 4; mt++) {
                const int r = wm + mt * 16 + g;
                ah[mt][0] = *(const uint32_t*)(pAh + r * MM_STRIDE_B + cbyte);
                ah[mt][1] = *(const uint32_t*)(pAh + (r + 8) * MM_STRIDE_B + cbyte);
                ah[mt][2] = *(const uint32_t*)(pAh + r * MM_STRIDE_B + cbyte + 16);
                ah[mt][3] = *(const uint32_t*)(pAh + (r + 8) * MM_STRIDE_B + cbyte + 16);
                al[mt][0] = *(const uint32_t*)(pAl + r * MM_STRIDE_B + cbyte);
                al[mt][1] = *(const uint32_t*)(pAl + (r + 8) * MM_STRIDE_B + cbyte);
                al[mt][2] = *(const uint32_t*)(pAl + r * MM_STRIDE_B + cbyte + 16);
                al[mt][3] = *(const uint32_t*)(pAl + (r + 8) * MM_STRIDE_B + cbyte + 16);
            }
            #pragma unroll
            for (int nt = 0; nt < 4; nt++) {
                const int n = wn + nt * 8 + g;
                bh[nt][0] = *(const uint32_t*)(pBh + n * MM_STRIDE_B + cbyte);
                bh[nt][1] = *(const uint32_t*)(pBh + n * MM_STRIDE_B + cbyte + 16);
                bl[nt][0] = *(const uint32_t*)(pBl + n * MM_STRIDE_B + cbyte);
                bl[nt][1] = *(const uint32_t*)(pBl + n * MM_STRIDE_B + cbyte + 16);
            }
            #pragma unroll
            for (int mt = 0; mt < 4; mt++)
                #pragma unroll
                for (int nt = 0; nt < 4; nt++) {
                    mma_bf16(acc[mt][nt], ah[mt], bh[nt]);
                    mma_bf16(acc[mt][nt], ah[mt], bl[nt]);
                    mma_bf16(acc[mt][nt], al[mt], bh[nt]);
                }
        }
        __syncthreads();
    }

    // ---- epilogue ----
    #pragma unroll
    for (int nt = 0; nt < 4; nt++) {
        const int col = col0 + wn + nt * 8 + 2 * tg;
        float b0 = 0.f, b1 = 0.f;
        if (ADD_BIAS) { b0 = bias[col]; b1 = bias[col + 1]; }
        #pragma unroll
        for (int mt = 0; mt < 4; mt++) {
            const int r = row0 + wm + mt * 16 + g;
            float2 v0, v1;
            v0.x = acc[mt][nt][0] + b0; v0.y = acc[mt][nt][1] + b1;
            v1.x = acc[mt][nt][2] + b0; v1.y = acc[mt][nt][3] + b1;
            *(float2*)(C + (long long)r * ldc + col)       = v0;
            *(float2*)(C + (long long)(r + 8) * ldc + col) = v1;
        }
    }
}

// ---------------- fp32 -> split bf16 (row-major keep) ----------------
__global__ void cvt_split(const float* __restrict__ src, __nv_bfloat16* __restrict__ h,
                          __nv_bfloat16* __restrict__ l, long long n)
{
    const long long i = ((long long)blockIdx.x * blockDim.x + threadIdx.x) * 4;
    if (i >= n) return;
    const float4 v = *(const float4*)(src + i);
    __nv_bfloat16 hb[4], lb[4];
    const float f[4] = {v.x, v.y, v.z, v.w};
    #pragma unroll
    for (int j = 0; j < 4; j++) {
        hb[j] = __float2bfloat16(f[j]);
        lb[j] = __float2bfloat16(f[j] - __bfloat162float(hb[j]));
    }
    *(uint2*)(h + i) = *(uint2*)hb;
    *(uint2*)(l + i) = *(uint2*)lb;
}

// ---------------- fp32 [K][N] -> split bf16 transposed [N][K] ----------------
__global__ void cvt_split_T(const float* __restrict__ W, __nv_bfloat16* __restrict__ h,
                            __nv_bfloat16* __restrict__ l, int K, int N)
{
    __shared__ float tile[32][33];
    const int k0 = blockIdx.y * 32;
    const int n0 = blockIdx.x * 32;
    const int tx = threadIdx.x;
    const int ty = threadIdx.y;
    #pragma unroll
    for (int i = ty; i < 32; i += 8)
        tile[i][tx] = W[(long long)(k0 + i) * N + n0 + tx];
    __syncthreads();
    #pragma unroll
    for (int i = ty; i < 32; i += 8) {
        const float v = tile[tx][i];
        const __nv_bfloat16 hb = __float2bfloat16(v);
        const __nv_bfloat16 lb = __float2bfloat16(v - __bfloat162float(hb));
        const long long o = (long long)(n0 + i) * K + k0 + tx;
        h[o] = hb; l[o] = lb;
    }
}

// ---------------- V: fp32 [bh][s][d] -> split bf16 transposed [bh][d][s] ----------
__global__ void v_transpose_split(const float* __restrict__ Vb,
                                  __nv_bfloat16* __restrict__ Vth,
                                  __nv_bfloat16* __restrict__ Vtl)
{
    __shared__ float tile[32][33];
    const int z  = blockIdx.z;
    const int ss0 = blockIdx.x * 32;   // s
    const int dd0 = blockIdx.y * 32;   // d
    const int tx = threadIdx.x;
    const int ty = threadIdx.y;
    const long long ib = (long long)z * Sk * HDim;
    const long long ob = (long long)z * HDim * Sk;
    #pragma unroll
    for (int i = ty; i < 32; i += 8)
        tile[i][tx] = Vb[ib + (long long)(ss0 + i) * HDim + dd0 + tx];
    __syncthreads();
    #pragma unroll
    for (int i = ty; i < 32; i += 8) {
        const float v = tile[tx][i];               // Vb[s0+tx][d0+i]
        const __nv_bfloat16 hb = __float2bfloat16(v);
        const __nv_bfloat16 lb = __float2bfloat16(v - __bfloat162float(hb));
        const long long o = ob + (long long)(dd0 + i) * Sk + ss0 + tx;
        Vth[o] = hb; Vtl[o] = lb;
    }
}

// ---------------- warp reduction helpers ----------------
__device__ __forceinline__ float warpSum(float v) {
    #pragma unroll
    for (int o = 16; o > 0; o >>= 1) v += __shfl_xor_sync(0xffffffffu, v, o);
    return v;
}
__device__ __forceinline__ float warpMax(float v) {
    #pragma unroll
    for (int o = 16; o > 0; o >>= 1) v = fmaxf(v, __shfl_xor_sync(0xffffffffu, v, o));
    return v;
}

__device__ __forceinline__ void split_write(float v, __nv_bfloat16* h, __nv_bfloat16* l, long long idx) {
    const __nv_bfloat16 hb = __float2bfloat16(v);
    h[idx] = hb;
    l[idx] = __float2bfloat16(v - __bfloat162float(hb));
}

// ---------------- QKV postprocess: RMSNorm + RoPE -> split bf16 Q,K; fp32 V ------
__global__ void qkv_post(const float* __restrict__ qkv, const float* __restrict__ pos,
                         const float* __restrict__ qw, const float* __restrict__ kw,
                         __nv_bfloat16* __restrict__ Qh, __nv_bfloat16* __restrict__ Ql,
                         __nv_bfloat16* __restrict__ Kh, __nv_bfloat16* __restrict__ Kl,
                         float* __restrict__ Vb)
{
    const int idx = blockIdx.x;
    const int h  = idx % Hn;
    const int bn = idx / Hn;
    const int n  = bn % Nq;
    const int b  = bn / Nq;
    const int d  = threadIdx.x;

    const float* row = qkv + (long long)bn * (3 * Cdim);
    const float qv = row[h * HDim + d];
    const float kv = row[Cdim + h * HDim + d];
    const float vv = row[2 * Cdim + h * HDim + d];

    __shared__ float sred[8];
    __shared__ float qs[HDim], ks[HDim];

    const float sq = warpSum(qv * qv);
    const float sk = warpSum(kv * kv);
    const int lane = d & 31, w = d >> 5;
    if (lane == 0) { sred[w] = sq; sred[4 + w] = sk; }
    __syncthreads();
    const float sumq = sred[0] + sred[1] + sred[2] + sred[3];
    const float sumk = sred[4] + sred[5] + sred[6] + sred[7];
    const float rq = rsqrtf(sumq * (1.0f / HDim) + EPSV);
    const float rk = rsqrtf(sumk * (1.0f / HDim) + EPSV);
    const float qn = qw[d] * qv * rq;
    const float kn = kw[d] * kv * rk;
    qs[d] = qn; ks[d] = kn;
    __syncthreads();

    float qo = qn, ko = kn;
    if (d < RD) {
        const int j = d & 31;
        const float c = pos[(n * 32 + j) * 2 + 0];
        const float s = pos[(n * 32 + j) * 2 + 1];
        if (d < RD / 2) { qo = qs[d] * c - qs[d + 32] * s;  ko = ks[d] * c - ks[d + 32] * s; }
        else            { qo = qs[d - 32] * s + qs[d] * c;  ko = ks[d - 32] * s + ks[d] * c; }
    }
    const long long qi = (((long long)(b * Hn + h)) * Nq + n) * HDim + d;
    const long long ki = (((long long)(b * Hn + h)) * Sk + n) * HDim + d;
    split_write(qo, Qh, Ql, qi);
    split_write(ko, Kh, Kl, ki);
    Vb[ki] = vv;
}

// ---------------- KV(y) postprocess ----------------
__global__ void kv_post(const float* __restrict__ kvr, const float* __restrict__ kw,
                        __nv_bfloat16* __restrict__ Kh, __nv_bfloat16* __restrict__ Kl,
                        float* __restrict__ Vb)
{
    const int idx = blockIdx.x;
    const int h  = idx % Hn;
    const int bm = idx / Hn;
    const int m  = bm % My;
    const int b  = bm / My;
    const int d  = threadIdx.x;

    const float* row = kvr + (long long)bm * (2 * Cdim);
    const float kv = row[h * HDim + d];
    const float vv = row[Cdim + h * HDim + d];

    __shared__ float sred[4];
    const float sk = warpSum(kv * kv);
    if ((d & 31) == 0) sred[d >> 5] = sk;
    __syncthreads();
    const float sumk = sred[0] + sred[1] + sred[2] + sred[3];
    const float rk = rsqrtf(sumk * (1.0f / HDim) + EPSV);
    const float kn = kw[d] * kv * rk;

    const long long ki = (((long long)(b * Hn + h)) * Sk + (Nq + m)) * HDim + d;
    split_write(kn, Kh, Kl, ki);
    Vb[ki] = vv;
}

__global__ void ybias_kernel(const float* __restrict__ ytw, float* __restrict__ yb)
{
    const int i = blockIdx.x * blockDim.x + threadIdx.x;
    if (i < Bsz * My) yb[i] = logf(fmaxf(ytw[i], 1e-4f));
}

// ---------------- softmax (scale + bias fused) -> split bf16 P ----------------
__global__ __launch_bounds__(256)
void softmax_kernel(const float* __restrict__ Sc, const float* __restrict__ yb,
                    __nv_bfloat16* __restrict__ Ph, __nv_bfloat16* __restrict__ Pl)
{
    const long long row = blockIdx.x;
    const int b = (int)(row / ((long long)Hn * Nq));
    const float* p = Sc + row * Sk;
    const int tid = threadIdx.x;

    float v[Sk / 256];
    float mx = -1e30f;
    #pragma unroll
    for (int i = 0; i < Sk / 256; i++) {
        const int col = tid + i * 256;
        float t = p[col] * SCALE;
        if (col >= Nq) t += yb[b * My + col - Nq];
        v[i] = t; mx = fmaxf(mx, t);
    }

    __shared__ float s[8];
    mx = warpMax(mx);
    if ((tid & 31) == 0) s[tid >> 5] = mx;
    __syncthreads();
    float mfull = s[0];
    #pragma unroll
    for (int w = 1; w < 8; w++) mfull = fmaxf(mfull, s[w]);
    __syncthreads();

    float sum = 0.f;
    #pragma unroll
    for (int i = 0; i < Sk / 256; i++) { v[i] = __expf(v[i] - mfull); sum += v[i]; }
    sum = warpSum(sum);
    if ((tid & 31) == 0) s[tid >> 5] = sum;
    __syncthreads();
    float tot = s[0];
    #pragma unroll
    for (int w = 1; w < 8; w++) tot += s[w];
    const float inv = 1.0f / tot;

    __nv_bfloat16* ph = Ph + row * Sk;
    __nv_bfloat16* pl = Pl + row * Sk;
    #pragma unroll
    for (int i = 0; i < Sk / 256; i++) {
        const int col = tid + i * 256;
        const float pv = v[i] * inv;
        const __nv_bfloat16 hb = __float2bfloat16(pv);
        ph[col] = hb;
        pl[col] = __float2bfloat16(pv - __bfloat162float(hb));
    }
}

// ---------------- launch ----------------
extern "C" void kernel_launch(void* const* d_in, const int* in_sizes, int n_in,
                              void* d_out, int out_size)
{
    const float* x    = (const float*)d_in[0];
    const float* y    = (const float*)d_in[1];
    const float* pos  = (const float*)d_in[2];
    const float* ytw  = (const float*)d_in[3];
    const float* Wqkv = (const float*)d_in[4];
    const float* Wkv  = (const float*)d_in[5];
    const float* qw   = (const float*)d_in[6];
    const float* kw   = (const float*)d_in[7];
    const float* Wproj= (const float*)d_in[8];
    const float* bproj= (const float*)d_in[9];
    float* out = (float*)d_out;

    float *qkv, *kvr, *Vb, *Sc, *Ob, *yb;
    cudaGetSymbolAddress((void**)&qkv, g_qkv);
    cudaGetSymbolAddress((void**)&kvr, g_kvr);
    cudaGetSymbolAddress((void**)&Vb,  g_Vb);
    cudaGetSymbolAddress((void**)&Sc,  g_Sc);
    cudaGetSymbolAddress((void**)&Ob,  g_Ob);
    cudaGetSymbolAddress((void**)&yb,  g_yb);

    __nv_bfloat16 *xh,*xl,*yh,*yl,*Wqh,*Wql,*Wkh,*Wkl,*Wph,*Wpl,*Obh,*Obl;
    __nv_bfloat16 *Qh,*Ql,*Kh,*Kl,*Vth,*Vtl,*Ph,*Pl;
    cudaGetSymbolAddress((void**)&xh, g_xh);   cudaGetSymbolAddress((void**)&xl, g_xl);
    cudaGetSymbolAddress((void**)&yh, g_yh);   cudaGetSymbolAddress((void**)&yl, g_yl);
    cudaGetSymbolAddress((void**)&Wqh, g_Wqkvh); cudaGetSymbolAddress((void**)&Wql, g_Wqkvl);
    cudaGetSymbolAddress((void**)&Wkh, g_Wkvh);  cudaGetSymbolAddress((void**)&Wkl, g_Wkvl);
    cudaGetSymbolAddress((void**)&Wph, g_Wph);   cudaGetSymbolAddress((void**)&Wpl, g_Wpl);
    cudaGetSymbolAddress((void**)&Obh, g_Obh);   cudaGetSymbolAddress((void**)&Obl, g_Obl);
    cudaGetSymbolAddress((void**)&Qh, g_Qh);     cudaGetSymbolAddress((void**)&Ql, g_Ql);
    cudaGetSymbolAddress((void**)&Kh, g_Kh);     cudaGetSymbolAddress((void**)&Kl, g_Kl);
    cudaGetSymbolAddress((void**)&Vth, g_Vth);   cudaGetSymbolAddress((void**)&Vtl, g_Vtl);
    cudaGetSymbolAddress((void**)&Ph, g_Ph);     cudaGetSymbolAddress((void**)&Pl, g_Pl);

    cudaFuncSetAttribute(mma_gemm<false>, cudaFuncAttributeMaxDynamicSharedMemorySize, MM_SMEM_B);
    cudaFuncSetAttribute(mma_gemm<true>,  cudaFuncAttributeMaxDynamicSharedMemorySize, MM_SMEM_B);

    const long long sQ  = (long long)Nq * HDim;
    const long long sKV = (long long)Sk * HDim;
    const long long sSc = (long long)Nq * Sk;

    // 0) split conversions: activations row-major, weights transposed to [N][K]
    auto cvt = [&](const float* s, __nv_bfloat16* h, __nv_bfloat16* l, long long n) {
        cvt_split<<<(int)((n / 4 + 255) / 256), 256>>>(s, h, l, n);
    };
    cvt(x, xh, xl, (long long)Bsz * Nq * Cdim);
    cvt(y, yh, yl, (long long)Bsz * My * Cdim);
    cvt_split_T<<<dim3(3 * Cdim / 32, Cdim / 32), dim3(32, 8)>>>(Wqkv, Wqh, Wql, Cdim, 3 * Cdim);
    cvt_split_T<<<dim3(2 * Cdim / 32, Cdim / 32), dim3(32, 8)>>>(Wkv,  Wkh, Wkl, Cdim, 2 * Cdim);
    cvt_split_T<<<dim3(Cdim / 32,     Cdim / 32), dim3(32, 8)>>>(Wproj, Wph, Wpl, Cdim, Cdim);

    // 1) QKV = x @ Wqkv  (HMMA split-bf16)
    mma_gemm<false><<<dim3(3 * Cdim / 128, Bsz * Nq / 128, 1), 256, MM_SMEM_B>>>(
        xh, xl, Wqh, Wql, qkv, nullptr, Cdim, 3 * Cdim, 0, 0, 0, 0, 1);

    // 2) KV = y @ Wkv    (HMMA split-bf16)
    mma_gemm<false><<<dim3(2 * Cdim / 128, Bsz * My / 128, 1), 256, MM_SMEM_B>>>(
        yh, yl, Wkh, Wkl, kvr, nullptr, Cdim, 2 * Cdim, 0, 0, 0, 0, 1);

    // 3) postprocess (emit split-bf16 Q,K directly; V fp32 then transpose-split)
    qkv_post<<<Bsz * Nq * Hn, HDim>>>(qkv, pos, qw, kw, Qh, Ql, Kh, Kl, Vb);
    kv_post<<<Bsz * My * Hn, HDim>>>(kvr, kw, Kh, Kl, Vb);
    ybias_kernel<<<(Bsz * My + 255) / 256, 256>>>(ytw, yb);
    v_transpose_split<<<dim3(Sk / 32, HDim / 32, Bsz * Hn), dim3(32, 8)>>>(Vb, Vth, Vtl);

    // 4) scores = Q @ K^T  batched over 24 (b,h)  (HMMA split-bf16)
    mma_gemm<false><<<dim3(Sk / 128, Nq / 128, Bsz * Hn), 256, MM_SMEM_B>>>(
        Qh, Ql, Kh, Kl, Sc, nullptr, HDim, Sk, sQ, sKV, sSc, 0, 1);

    // 5) softmax -> split bf16 P
    softmax_kernel<<<Bsz * Hn * Nq, 256>>>(Sc, yb, Ph, Pl);

    // 6) O = P @ V  batched (HMMA split-bf16), scatter into [b][n][h*128]
    mma_gemm<false><<<dim3(HDim / 128, Nq / 128, Bsz * Hn), 256, MM_SMEM_B>>>(
        Ph, Pl, Vth, Vtl, Ob, nullptr, Sk, Cdim,
        sSc, sKV, (long long)Nq * Cdim, (long long)HDim, Hn);

    // 7) convert O, then out = O @ Wproj + bproj (HMMA split-bf16)
    cvt(Ob, Obh, Obl, (long long)Bsz * Nq * Cdim);
    mma_gemm<true><<<dim3(Cdim / 128, Bsz * Nq / 128, 1), 256, MM_SMEM_B>>>(
        Obh, Obl, Wph, Wpl, out, bproj, Cdim, Cdim, 0, 0, 0, 0, 1);
}